// round 1
// baseline (speedup 1.0000x reference)
#include <cuda_runtime.h>
#include <math.h>

// ---------------------------------------------------------------------------
// Problem constants
//   x      [B=2, T=2048, C=1024]  fp32
//   W_qkv  [3C=3072, C=1024]      fp32   (y = x @ W^T)
//   W_out  [C=1024, C=1024]       fp32
//   out    [B, T, C]              fp32
// ---------------------------------------------------------------------------
#define BATCH   2
#define SEQ     2048
#define DMODEL  1024
#define NHEADS  16
#define HDIM    64
#define MROWS   (BATCH * SEQ)          // 4096
#define QKV_N   (3 * DMODEL)           // 3072

// Scratch: qkv projection result and attention output (pre out-proj)
__device__ float g_qkv[(size_t)MROWS * QKV_N];   // [4096, 3072]
__device__ float g_att[(size_t)MROWS * DMODEL];  // [4096, 1024]

// ---------------------------------------------------------------------------
// SGEMM:  C[M,N] = A[M,K] * B[N,K]^T   (both operands K-major, fp32)
// 128x128 block tile, BK=8, 8x8 per thread, 256 threads.
// All dims divisible by tile sizes (M=4096, N in {3072,1024}, K=1024).
// ---------------------------------------------------------------------------
#define GBM 128
#define GBN 128
#define GBK 8

__global__ __launch_bounds__(256) void sgemm_nt(
    const float* __restrict__ A,
    const float* __restrict__ B,
    float* __restrict__ C,
    int M, int N, int K)
{
    __shared__ float As[GBK][GBM];
    __shared__ float Bs[GBK][GBN];

    const int tid = threadIdx.x;
    const int ty = tid >> 4;       // 0..15
    const int tx = tid & 15;       // 0..15
    const int brow = blockIdx.y * GBM;
    const int bcol = blockIdx.x * GBN;

    // each thread loads one float4 of A and one of B per BK-step
    const int lrow = tid >> 1;           // 0..127
    const int lk   = (tid & 1) * 4;      // 0 or 4
    const float* Ag = A + (size_t)(brow + lrow) * K + lk;
    const float* Bg = B + (size_t)(bcol + lrow) * K + lk;

    float acc[8][8];
#pragma unroll
    for (int i = 0; i < 8; i++)
#pragma unroll
        for (int j = 0; j < 8; j++) acc[i][j] = 0.f;

    for (int k0 = 0; k0 < K; k0 += GBK) {
        float4 av = *(const float4*)(Ag + k0);
        float4 bv = *(const float4*)(Bg + k0);
        __syncthreads();   // previous compute done before overwrite
        As[lk + 0][lrow] = av.x;
        As[lk + 1][lrow] = av.y;
        As[lk + 2][lrow] = av.z;
        As[lk + 3][lrow] = av.w;
        Bs[lk + 0][lrow] = bv.x;
        Bs[lk + 1][lrow] = bv.y;
        Bs[lk + 2][lrow] = bv.z;
        Bs[lk + 3][lrow] = bv.w;
        __syncthreads();

#pragma unroll
        for (int k = 0; k < GBK; k++) {
            float a[8], b[8];
            *(float4*)&a[0] = *(const float4*)&As[k][ty * 8];
            *(float4*)&a[4] = *(const float4*)&As[k][ty * 8 + 4];
            *(float4*)&b[0] = *(const float4*)&Bs[k][tx * 8];
            *(float4*)&b[4] = *(const float4*)&Bs[k][tx * 8 + 4];
#pragma unroll
            for (int i = 0; i < 8; i++)
#pragma unroll
                for (int j = 0; j < 8; j++)
                    acc[i][j] += a[i] * b[j];
        }
    }

    float* Cp = C + (size_t)(brow + ty * 8) * N + bcol + tx * 8;
#pragma unroll
    for (int i = 0; i < 8; i++) {
        *(float4*)(Cp + (size_t)i * N)     = make_float4(acc[i][0], acc[i][1], acc[i][2], acc[i][3]);
        *(float4*)(Cp + (size_t)i * N + 4) = make_float4(acc[i][4], acc[i][5], acc[i][6], acc[i][7]);
    }
}

// ---------------------------------------------------------------------------
// Flash attention (causal), fp32.
// Grid: (T/64 query tiles, B*H).  Block: 256 threads (ty=tid/16, tx=tid%16).
// Br = Bc = 64, D = 64. 4x4 fragment per thread.
// Smem: Qs[d][q] 16KB, KPs 16KB (K as [d][k], reused to hold P as [q][k]),
//       Vs[k][d] 16KB  -> 48KB static.
// ---------------------------------------------------------------------------
__global__ __launch_bounds__(256) void flash_attn(
    const float* __restrict__ qkv,   // [MROWS, 3072]
    float* __restrict__ att)         // [MROWS, 1024]
{
    __shared__ float Qs[64][64];   // [d][q]
    __shared__ float KPs[64][64];  // K: [d][key]; later P: [q][key]
    __shared__ float Vs[64][64];   // [key][d]

    const int tid = threadIdx.x;
    const int ty = tid >> 4;       // 0..15
    const int tx = tid & 15;       // 0..15
    const int qt = (int)gridDim.x - 1 - (int)blockIdx.x;  // heavy tiles first
    const int bh = blockIdx.y;
    const int b  = bh >> 4;
    const int h  = bh & 15;

    const int rowbase = b * SEQ;       // batch base row
    const int q0 = qt * 64;            // query tile start (in T)

    // cooperative loader indices: thread -> (row 0..63, d-chunk of 16)
    const int lr  = tid >> 2;          // 0..63
    const int ldc = (tid & 3) * 16;    // 0,16,32,48

    // ---- load Q tile transposed: Qs[d][q] ----
    {
        const float* src = qkv + (size_t)(rowbase + q0 + lr) * QKV_N + h * HDIM + ldc;
#pragma unroll
        for (int u = 0; u < 4; u++) {
            float4 v = *(const float4*)(src + u * 4);
            Qs[ldc + u * 4 + 0][lr] = v.x;
            Qs[ldc + u * 4 + 1][lr] = v.y;
            Qs[ldc + u * 4 + 2][lr] = v.z;
            Qs[ldc + u * 4 + 3][lr] = v.w;
        }
    }

    float m_i[4], l_i[4], acc_o[4][4];
#pragma unroll
    for (int i = 0; i < 4; i++) {
        m_i[i] = -1e30f;
        l_i[i] = 0.f;
#pragma unroll
        for (int j = 0; j < 4; j++) acc_o[i][j] = 0.f;
    }

    const float scale = 0.125f;   // 1/sqrt(64)

    for (int jt = 0; jt <= qt; jt++) {
        __syncthreads();  // prev iter's P/V reads done before overwrite

        // ---- load K (transposed) and V tiles ----
        {
            const float* ksrc = qkv + (size_t)(rowbase + jt * 64 + lr) * QKV_N + DMODEL     + h * HDIM + ldc;
            const float* vsrc = qkv + (size_t)(rowbase + jt * 64 + lr) * QKV_N + 2 * DMODEL + h * HDIM + ldc;
#pragma unroll
            for (int u = 0; u < 4; u++) {
                float4 kv = *(const float4*)(ksrc + u * 4);
                KPs[ldc + u * 4 + 0][lr] = kv.x;
                KPs[ldc + u * 4 + 1][lr] = kv.y;
                KPs[ldc + u * 4 + 2][lr] = kv.z;
                KPs[ldc + u * 4 + 3][lr] = kv.w;
                *(float4*)&Vs[lr][ldc + u * 4] = *(const float4*)(vsrc + u * 4);
            }
        }
        __syncthreads();

        // ---- S = Q K^T (4x4 fragment) ----
        float s[4][4];
#pragma unroll
        for (int i = 0; i < 4; i++)
#pragma unroll
            for (int j = 0; j < 4; j++) s[i][j] = 0.f;

#pragma unroll
        for (int d = 0; d < 64; d++) {
            float4 a = *(const float4*)&Qs[d][ty * 4];
            float4 bb = *(const float4*)&KPs[d][tx * 4];
            s[0][0] += a.x * bb.x; s[0][1] += a.x * bb.y; s[0][2] += a.x * bb.z; s[0][3] += a.x * bb.w;
            s[1][0] += a.y * bb.x; s[1][1] += a.y * bb.y; s[1][2] += a.y * bb.z; s[1][3] += a.y * bb.w;
            s[2][0] += a.z * bb.x; s[2][1] += a.z * bb.y; s[2][2] += a.z * bb.z; s[2][3] += a.z * bb.w;
            s[3][0] += a.w * bb.x; s[3][1] += a.w * bb.y; s[3][2] += a.w * bb.z; s[3][3] += a.w * bb.w;
        }

        // ---- scale + causal mask (diagonal tile only) ----
        if (jt == qt) {
#pragma unroll
            for (int i = 0; i < 4; i++) {
                int qloc = ty * 4 + i;
#pragma unroll
                for (int j = 0; j < 4; j++) {
                    int kloc = tx * 4 + j;
                    s[i][j] = (kloc <= qloc) ? s[i][j] * scale : -1e30f;
                }
            }
        } else {
#pragma unroll
            for (int i = 0; i < 4; i++)
#pragma unroll
                for (int j = 0; j < 4; j++) s[i][j] *= scale;
        }

        // ---- online softmax (row = 16 consecutive lanes) ----
#pragma unroll
        for (int i = 0; i < 4; i++) {
            float mx = fmaxf(fmaxf(s[i][0], s[i][1]), fmaxf(s[i][2], s[i][3]));
#pragma unroll
            for (int off = 8; off >= 1; off >>= 1)
                mx = fmaxf(mx, __shfl_xor_sync(0xffffffffu, mx, off));
            float mn = fmaxf(m_i[i], mx);
            float sum = 0.f;
#pragma unroll
            for (int j = 0; j < 4; j++) {
                float p = __expf(s[i][j] - mn);
                s[i][j] = p;
                sum += p;
            }
#pragma unroll
            for (int off = 8; off >= 1; off >>= 1)
                sum += __shfl_xor_sync(0xffffffffu, sum, off);
            float alpha = __expf(m_i[i] - mn);
            l_i[i] = l_i[i] * alpha + sum;
            m_i[i] = mn;
#pragma unroll
            for (int j = 0; j < 4; j++) acc_o[i][j] *= alpha;
        }

        __syncthreads();   // all S-GEMM reads of KPs done
        // ---- write P into KPs as [q][key] ----
#pragma unroll
        for (int i = 0; i < 4; i++)
            *(float4*)&KPs[ty * 4 + i][tx * 4] = make_float4(s[i][0], s[i][1], s[i][2], s[i][3]);
        __syncthreads();

        // ---- O += P V ----
#pragma unroll
        for (int k = 0; k < 64; k++) {
            float4 v = *(const float4*)&Vs[k][tx * 4];
            float a0 = KPs[ty * 4 + 0][k];
            float a1 = KPs[ty * 4 + 1][k];
            float a2 = KPs[ty * 4 + 2][k];
            float a3 = KPs[ty * 4 + 3][k];
            acc_o[0][0] += a0 * v.x; acc_o[0][1] += a0 * v.y; acc_o[0][2] += a0 * v.z; acc_o[0][3] += a0 * v.w;
            acc_o[1][0] += a1 * v.x; acc_o[1][1] += a1 * v.y; acc_o[1][2] += a1 * v.z; acc_o[1][3] += a1 * v.w;
            acc_o[2][0] += a2 * v.x; acc_o[2][1] += a2 * v.y; acc_o[2][2] += a2 * v.z; acc_o[2][3] += a2 * v.w;
            acc_o[3][0] += a3 * v.x; acc_o[3][1] += a3 * v.y; acc_o[3][2] += a3 * v.z; acc_o[3][3] += a3 * v.w;
        }
    }

    // ---- epilogue: normalize and write [B,T,C] with head interleave ----
#pragma unroll
    for (int i = 0; i < 4; i++) {
        float inv = 1.f / l_i[i];
        int row = rowbase + q0 + ty * 4 + i;
        float* dst = att + (size_t)row * DMODEL + h * HDIM + tx * 4;
        *(float4*)dst = make_float4(acc_o[i][0] * inv, acc_o[i][1] * inv,
                                    acc_o[i][2] * inv, acc_o[i][3] * inv);
    }
}

// ---------------------------------------------------------------------------
// Launch
// ---------------------------------------------------------------------------
extern "C" void kernel_launch(void* const* d_in, const int* in_sizes, int n_in,
                              void* d_out, int out_size)
{
    (void)in_sizes; (void)n_in; (void)out_size;
    const float* x     = (const float*)d_in[0];
    const float* W_qkv = (const float*)d_in[1];
    const float* W_out = (const float*)d_in[2];
    float* out = (float*)d_out;

    float* qkv = nullptr;
    float* att = nullptr;
    cudaGetSymbolAddress((void**)&qkv, g_qkv);
    cudaGetSymbolAddress((void**)&att, g_att);

    // 1) QKV projection: [4096,1024] x [3072,1024]^T -> [4096,3072]
    sgemm_nt<<<dim3(QKV_N / GBN, MROWS / GBM), 256>>>(x, W_qkv, qkv, MROWS, QKV_N, DMODEL);

    // 2) causal flash attention -> [4096,1024] (heads re-interleaved)
    flash_attn<<<dim3(SEQ / 64, BATCH * NHEADS), 256>>>(qkv, att);

    // 3) output projection: [4096,1024] x [1024,1024]^T -> out
    sgemm_nt<<<dim3(DMODEL / GBN, MROWS / GBM), 256>>>(att, W_out, out, MROWS, DMODEL, DMODEL);
}

// round 3
// speedup vs baseline: 1.4451x; 1.4451x over previous
#include <cuda_runtime.h>
#include <cuda_bf16.h>
#include <math.h>
#include <stdint.h>

// ---------------------------------------------------------------------------
// Problem constants
// ---------------------------------------------------------------------------
#define BATCH   2
#define SEQ     2048
#define DMODEL  1024
#define NHEADS  16
#define HDIM    64
#define MROWS   (BATCH * SEQ)          // 4096
#define QKV_N   (3 * DMODEL)           // 3072

// ---------------------------------------------------------------------------
// Scratch (__device__ globals — no allocation allowed)
// ---------------------------------------------------------------------------
__device__ float         g_qkv[(size_t)MROWS * QKV_N];    // 48 MB fp32
__device__ __nv_bfloat16 g_xh[(size_t)MROWS * DMODEL];
__device__ __nv_bfloat16 g_xl[(size_t)MROWS * DMODEL];
__device__ __nv_bfloat16 g_wqh[(size_t)QKV_N * DMODEL];
__device__ __nv_bfloat16 g_wql[(size_t)QKV_N * DMODEL];
__device__ __nv_bfloat16 g_woh[(size_t)DMODEL * DMODEL];
__device__ __nv_bfloat16 g_wol[(size_t)DMODEL * DMODEL];
__device__ __nv_bfloat16 g_ath[(size_t)MROWS * DMODEL];
__device__ __nv_bfloat16 g_atl[(size_t)MROWS * DMODEL];

// ---------------------------------------------------------------------------
// mma.sync / ldmatrix helpers (sm_80+ PTX — safe on compute_103 target)
// ---------------------------------------------------------------------------
__device__ __forceinline__ uint32_t smem_u32(const void* p) {
    uint32_t a;
    asm("{ .reg .u64 t; cvta.to.shared.u64 t, %1; cvt.u32.u64 %0, t; }" : "=r"(a) : "l"(p));
    return a;
}
__device__ __forceinline__ void ldsm_x4(uint32_t& r0, uint32_t& r1, uint32_t& r2,
                                        uint32_t& r3, uint32_t addr) {
    asm volatile("ldmatrix.sync.aligned.m8n8.x4.shared.b16 {%0,%1,%2,%3}, [%4];"
                 : "=r"(r0), "=r"(r1), "=r"(r2), "=r"(r3) : "r"(addr));
}
__device__ __forceinline__ void mma16816(float* d, const uint32_t* a, const uint32_t* b) {
    asm volatile(
        "mma.sync.aligned.m16n8k16.row.col.f32.bf16.bf16.f32 "
        "{%0,%1,%2,%3}, {%4,%5,%6,%7}, {%8,%9}, {%0,%1,%2,%3};"
        : "+f"(d[0]), "+f"(d[1]), "+f"(d[2]), "+f"(d[3])
        : "r"(a[0]), "r"(a[1]), "r"(a[2]), "r"(a[3]), "r"(b[0]), "r"(b[1]));
}

// ---------------------------------------------------------------------------
// split fp32 -> bf16 hi + bf16 lo
// ---------------------------------------------------------------------------
__global__ __launch_bounds__(256) void split_bf16(
    const float* __restrict__ in, __nv_bfloat16* __restrict__ hi,
    __nv_bfloat16* __restrict__ lo, int n4)
{
    int i = blockIdx.x * 256 + threadIdx.x;
    if (i >= n4) return;
    float4 v = ((const float4*)in)[i];
    __nv_bfloat16 h0 = __float2bfloat16(v.x);
    __nv_bfloat16 h1 = __float2bfloat16(v.y);
    __nv_bfloat16 h2 = __float2bfloat16(v.z);
    __nv_bfloat16 h3 = __float2bfloat16(v.w);
    __nv_bfloat16 l0 = __float2bfloat16(v.x - __bfloat162float(h0));
    __nv_bfloat16 l1 = __float2bfloat16(v.y - __bfloat162float(h1));
    __nv_bfloat16 l2 = __float2bfloat16(v.z - __bfloat162float(h2));
    __nv_bfloat16 l3 = __float2bfloat16(v.w - __bfloat162float(h3));
    ((__nv_bfloat162*)hi)[2 * i]     = __nv_bfloat162(h0, h1);
    ((__nv_bfloat162*)hi)[2 * i + 1] = __nv_bfloat162(h2, h3);
    ((__nv_bfloat162*)lo)[2 * i]     = __nv_bfloat162(l0, l1);
    ((__nv_bfloat162*)lo)[2 * i + 1] = __nv_bfloat162(l2, l3);
}

// ---------------------------------------------------------------------------
// HMMA GEMM, bf16x3-split:  C[M,N] = A[M,K] * B[N,K]^T  (fp32-accurate)
// 128x128 CTA tile, BK=32, 8 warps x (32m x 64n) warp tiles, m16n8k16.
// Smem pitch 40 bf16 (80B) -> conflict-free ldmatrix.
// ---------------------------------------------------------------------------
#define BM 128
#define BN 128
#define BK 32
#define PITCH 40

__global__ __launch_bounds__(256) void gemm_hmma(
    const __nv_bfloat16* __restrict__ Ah, const __nv_bfloat16* __restrict__ Al,
    const __nv_bfloat16* __restrict__ Bh, const __nv_bfloat16* __restrict__ Bl,
    float* __restrict__ C, int M, int N, int K)
{
    __shared__ __nv_bfloat16 sAh[BM * PITCH];
    __shared__ __nv_bfloat16 sAl[BM * PITCH];
    __shared__ __nv_bfloat16 sBh[BN * PITCH];
    __shared__ __nv_bfloat16 sBl[BN * PITCH];

    const int tid = threadIdx.x;
    const int wid = tid >> 5;
    const int lid = tid & 31;
    const int warp_m = (wid & 3) * 32;
    const int warp_n = (wid >> 2) * 64;
    const int brow = blockIdx.y * BM;
    const int bcol = blockIdx.x * BN;

    const uint32_t uAh = smem_u32(sAh), uAl = smem_u32(sAl);
    const uint32_t uBh = smem_u32(sBh), uBl = smem_u32(sBl);

    float acc[2][8][4];
#pragma unroll
    for (int mf = 0; mf < 2; mf++)
#pragma unroll
        for (int nf = 0; nf < 8; nf++)
#pragma unroll
            for (int c = 0; c < 4; c++) acc[mf][nf][c] = 0.f;

    // per-thread ldmatrix row offsets
    const int a_row = warp_m + (lid & 15);          // + mf*16
    const int a_ko  = (lid >> 4) * 8;               // element offset within kstep
    const int b_row = warp_n + (lid & 7) + ((lid >> 4) & 1) * 8;  // + pair*16
    const int b_ko  = ((lid >> 3) & 1) * 8;

    // loader mapping: tile = 512 uint4; thread covers v = tid, tid+256
    const int r0 = tid >> 2, c0 = (tid & 3);              // row, 16B chunk
    const int r1 = (tid + 256) >> 2, c1 = ((tid + 256) & 3);

    for (int kc = 0; kc < K; kc += BK) {
        __syncthreads();
        {
            size_t gA0 = (size_t)(brow + r0) * K + kc + c0 * 8;
            size_t gA1 = (size_t)(brow + r1) * K + kc + c1 * 8;
            size_t gB0 = (size_t)(bcol + r0) * K + kc + c0 * 8;
            size_t gB1 = (size_t)(bcol + r1) * K + kc + c1 * 8;
            *(uint4*)&sAh[r0 * PITCH + c0 * 8] = *(const uint4*)(Ah + gA0);
            *(uint4*)&sAh[r1 * PITCH + c1 * 8] = *(const uint4*)(Ah + gA1);
            *(uint4*)&sAl[r0 * PITCH + c0 * 8] = *(const uint4*)(Al + gA0);
            *(uint4*)&sAl[r1 * PITCH + c1 * 8] = *(const uint4*)(Al + gA1);
            *(uint4*)&sBh[r0 * PITCH + c0 * 8] = *(const uint4*)(Bh + gB0);
            *(uint4*)&sBh[r1 * PITCH + c1 * 8] = *(const uint4*)(Bh + gB1);
            *(uint4*)&sBl[r0 * PITCH + c0 * 8] = *(const uint4*)(Bl + gB0);
            *(uint4*)&sBl[r1 * PITCH + c1 * 8] = *(const uint4*)(Bl + gB1);
        }
        __syncthreads();

#pragma unroll
        for (int ks = 0; ks < 2; ks++) {
            uint32_t ah[2][4], al[2][4];
#pragma unroll
            for (int mf = 0; mf < 2; mf++) {
                uint32_t off = ((a_row + mf * 16) * PITCH + ks * 16 + a_ko) * 2;
                ldsm_x4(ah[mf][0], ah[mf][1], ah[mf][2], ah[mf][3], uAh + off);
                ldsm_x4(al[mf][0], al[mf][1], al[mf][2], al[mf][3], uAl + off);
            }
            uint32_t bh[8][2], bl[8][2];
#pragma unroll
            for (int p = 0; p < 4; p++) {
                uint32_t off = ((b_row + p * 16) * PITCH + ks * 16 + b_ko) * 2;
                ldsm_x4(bh[2 * p][0], bh[2 * p][1], bh[2 * p + 1][0], bh[2 * p + 1][1], uBh + off);
                ldsm_x4(bl[2 * p][0], bl[2 * p][1], bl[2 * p + 1][0], bl[2 * p + 1][1], uBl + off);
            }
#pragma unroll
            for (int mf = 0; mf < 2; mf++)
#pragma unroll
                for (int nf = 0; nf < 8; nf++) {
                    mma16816(acc[mf][nf], ah[mf], bh[nf]);
                    mma16816(acc[mf][nf], ah[mf], bl[nf]);
                    mma16816(acc[mf][nf], al[mf], bh[nf]);
                }
        }
    }

    // epilogue: direct fragment stores (float2, 8B aligned)
    const int er = lid >> 2;        // 0..7
    const int ec = (lid & 3) * 2;   // 0,2,4,6
#pragma unroll
    for (int mf = 0; mf < 2; mf++) {
#pragma unroll
        for (int nf = 0; nf < 8; nf++) {
            int row = brow + warp_m + mf * 16 + er;
            int col = bcol + warp_n + nf * 8 + ec;
            *(float2*)&C[(size_t)row * N + col] = make_float2(acc[mf][nf][0], acc[mf][nf][1]);
            *(float2*)&C[(size_t)(row + 8) * N + col] = make_float2(acc[mf][nf][2], acc[mf][nf][3]);
        }
    }
}

// ---------------------------------------------------------------------------
// Flash attention (causal), fp32 SIMT; epilogue emits bf16 hi/lo split.
// ---------------------------------------------------------------------------
__global__ __launch_bounds__(256) void flash_attn(
    const float* __restrict__ qkv,            // [MROWS, 3072]
    __nv_bfloat16* __restrict__ ath,          // [MROWS, 1024]
    __nv_bfloat16* __restrict__ atl)
{
    __shared__ float Qs[64][64];
    __shared__ float KPs[64][64];
    __shared__ float Vs[64][64];

    const int tid = threadIdx.x;
    const int ty = tid >> 4;
    const int tx = tid & 15;
    const int qt = (int)gridDim.x - 1 - (int)blockIdx.x;
    const int bh = blockIdx.y;
    const int b = bh >> 4;
    const int h = bh & 15;

    const int rowbase = b * SEQ;
    const int q0 = qt * 64;
    const int lr = tid >> 2;
    const int ldc = (tid & 3) * 16;

    {
        const float* src = qkv + (size_t)(rowbase + q0 + lr) * QKV_N + h * HDIM + ldc;
#pragma unroll
        for (int u = 0; u < 4; u++) {
            float4 v = *(const float4*)(src + u * 4);
            Qs[ldc + u * 4 + 0][lr] = v.x;
            Qs[ldc + u * 4 + 1][lr] = v.y;
            Qs[ldc + u * 4 + 2][lr] = v.z;
            Qs[ldc + u * 4 + 3][lr] = v.w;
        }
    }

    float m_i[4], l_i[4], acc_o[4][4];
#pragma unroll
    for (int i = 0; i < 4; i++) {
        m_i[i] = -1e30f;
        l_i[i] = 0.f;
#pragma unroll
        for (int j = 0; j < 4; j++) acc_o[i][j] = 0.f;
    }
    const float scale = 0.125f;

    for (int jt = 0; jt <= qt; jt++) {
        __syncthreads();
        {
            const float* ksrc = qkv + (size_t)(rowbase + jt * 64 + lr) * QKV_N + DMODEL + h * HDIM + ldc;
            const float* vsrc = qkv + (size_t)(rowbase + jt * 64 + lr) * QKV_N + 2 * DMODEL + h * HDIM + ldc;
#pragma unroll
            for (int u = 0; u < 4; u++) {
                float4 kv = *(const float4*)(ksrc + u * 4);
                KPs[ldc + u * 4 + 0][lr] = kv.x;
                KPs[ldc + u * 4 + 1][lr] = kv.y;
                KPs[ldc + u * 4 + 2][lr] = kv.z;
                KPs[ldc + u * 4 + 3][lr] = kv.w;
                *(float4*)&Vs[lr][ldc + u * 4] = *(const float4*)(vsrc + u * 4);
            }
        }
        __syncthreads();

        float s[4][4];
#pragma unroll
        for (int i = 0; i < 4; i++)
#pragma unroll
            for (int j = 0; j < 4; j++) s[i][j] = 0.f;

#pragma unroll
        for (int d = 0; d < 64; d++) {
            float4 a = *(const float4*)&Qs[d][ty * 4];
            float4 bb = *(const float4*)&KPs[d][tx * 4];
            s[0][0] += a.x * bb.x; s[0][1] += a.x * bb.y; s[0][2] += a.x * bb.z; s[0][3] += a.x * bb.w;
            s[1][0] += a.y * bb.x; s[1][1] += a.y * bb.y; s[1][2] += a.y * bb.z; s[1][3] += a.y * bb.w;
            s[2][0] += a.z * bb.x; s[2][1] += a.z * bb.y; s[2][2] += a.z * bb.z; s[2][3] += a.z * bb.w;
            s[3][0] += a.w * bb.x; s[3][1] += a.w * bb.y; s[3][2] += a.w * bb.z; s[3][3] += a.w * bb.w;
        }

        if (jt == qt) {
#pragma unroll
            for (int i = 0; i < 4; i++) {
                int qloc = ty * 4 + i;
#pragma unroll
                for (int j = 0; j < 4; j++) {
                    int kloc = tx * 4 + j;
                    s[i][j] = (kloc <= qloc) ? s[i][j] * scale : -1e30f;
                }
            }
        } else {
#pragma unroll
            for (int i = 0; i < 4; i++)
#pragma unroll
                for (int j = 0; j < 4; j++) s[i][j] *= scale;
        }

#pragma unroll
        for (int i = 0; i < 4; i++) {
            float mx = fmaxf(fmaxf(s[i][0], s[i][1]), fmaxf(s[i][2], s[i][3]));
#pragma unroll
            for (int off = 8; off >= 1; off >>= 1)
                mx = fmaxf(mx, __shfl_xor_sync(0xffffffffu, mx, off));
            float mn = fmaxf(m_i[i], mx);
            float sum = 0.f;
#pragma unroll
            for (int j = 0; j < 4; j++) {
                float p = __expf(s[i][j] - mn);
                s[i][j] = p;
                sum += p;
            }
#pragma unroll
            for (int off = 8; off >= 1; off >>= 1)
                sum += __shfl_xor_sync(0xffffffffu, sum, off);
            float alpha = __expf(m_i[i] - mn);
            l_i[i] = l_i[i] * alpha + sum;
            m_i[i] = mn;
#pragma unroll
            for (int j = 0; j < 4; j++) acc_o[i][j] *= alpha;
        }

        __syncthreads();
#pragma unroll
        for (int i = 0; i < 4; i++)
            *(float4*)&KPs[ty * 4 + i][tx * 4] = make_float4(s[i][0], s[i][1], s[i][2], s[i][3]);
        __syncthreads();

#pragma unroll
        for (int k = 0; k < 64; k++) {
            float4 v = *(const float4*)&Vs[k][tx * 4];
            float a0 = KPs[ty * 4 + 0][k];
            float a1 = KPs[ty * 4 + 1][k];
            float a2 = KPs[ty * 4 + 2][k];
            float a3 = KPs[ty * 4 + 3][k];
            acc_o[0][0] += a0 * v.x; acc_o[0][1] += a0 * v.y; acc_o[0][2] += a0 * v.z; acc_o[0][3] += a0 * v.w;
            acc_o[1][0] += a1 * v.x; acc_o[1][1] += a1 * v.y; acc_o[1][2] += a1 * v.z; acc_o[1][3] += a1 * v.w;
            acc_o[2][0] += a2 * v.x; acc_o[2][1] += a2 * v.y; acc_o[2][2] += a2 * v.z; acc_o[2][3] += a2 * v.w;
            acc_o[3][0] += a3 * v.x; acc_o[3][1] += a3 * v.y; acc_o[3][2] += a3 * v.z; acc_o[3][3] += a3 * v.w;
        }
    }

#pragma unroll
    for (int i = 0; i < 4; i++) {
        float inv = 1.f / l_i[i];
        int row = rowbase + q0 + ty * 4 + i;
        size_t off = (size_t)row * DMODEL + h * HDIM + tx * 4;
        float v0 = acc_o[i][0] * inv, v1 = acc_o[i][1] * inv;
        float v2 = acc_o[i][2] * inv, v3 = acc_o[i][3] * inv;
        __nv_bfloat16 h0 = __float2bfloat16(v0), h1 = __float2bfloat16(v1);
        __nv_bfloat16 h2 = __float2bfloat16(v2), h3 = __float2bfloat16(v3);
        __nv_bfloat16 l0 = __float2bfloat16(v0 - __bfloat162float(h0));
        __nv_bfloat16 l1 = __float2bfloat16(v1 - __bfloat162float(h1));
        __nv_bfloat16 l2 = __float2bfloat16(v2 - __bfloat162float(h2));
        __nv_bfloat16 l3 = __float2bfloat16(v3 - __bfloat162float(h3));
        __nv_bfloat162* ph = (__nv_bfloat162*)(ath + off);
        __nv_bfloat162* pl = (__nv_bfloat162*)(atl + off);
        ph[0] = __nv_bfloat162(h0, h1); ph[1] = __nv_bfloat162(h2, h3);
        pl[0] = __nv_bfloat162(l0, l1); pl[1] = __nv_bfloat162(l2, l3);
    }
}

// ---------------------------------------------------------------------------
// Launch
// ---------------------------------------------------------------------------
extern "C" void kernel_launch(void* const* d_in, const int* in_sizes, int n_in,
                              void* d_out, int out_size)
{
    (void)in_sizes; (void)n_in; (void)out_size;
    const float* x     = (const float*)d_in[0];
    const float* W_qkv = (const float*)d_in[1];
    const float* W_out = (const float*)d_in[2];
    float* out = (float*)d_out;

    float* qkv;
    __nv_bfloat16 *xh, *xl, *wqh, *wql, *woh, *wol, *ath, *atl;
    cudaGetSymbolAddress((void**)&qkv, g_qkv);
    cudaGetSymbolAddress((void**)&xh, g_xh);
    cudaGetSymbolAddress((void**)&xl, g_xl);
    cudaGetSymbolAddress((void**)&wqh, g_wqh);
    cudaGetSymbolAddress((void**)&wql, g_wql);
    cudaGetSymbolAddress((void**)&woh, g_woh);
    cudaGetSymbolAddress((void**)&wol, g_wol);
    cudaGetSymbolAddress((void**)&ath, g_ath);
    cudaGetSymbolAddress((void**)&atl, g_atl);

    // split inputs into bf16 hi/lo
    split_bf16<<<(MROWS * DMODEL / 4 + 255) / 256, 256>>>(x, xh, xl, MROWS * DMODEL / 4);
    split_bf16<<<(QKV_N * DMODEL / 4 + 255) / 256, 256>>>(W_qkv, wqh, wql, QKV_N * DMODEL / 4);
    split_bf16<<<(DMODEL * DMODEL / 4 + 255) / 256, 256>>>(W_out, woh, wol, DMODEL * DMODEL / 4);

    // 1) QKV projection (HMMA bf16x3)
    gemm_hmma<<<dim3(QKV_N / BN, MROWS / BM), 256>>>(
        xh, xl, wqh, wql, qkv, MROWS, QKV_N, DMODEL);

    // 2) causal flash attention (fp32 SIMT) -> bf16 hi/lo
    flash_attn<<<dim3(SEQ / 64, BATCH * NHEADS), 256>>>(qkv, ath, atl);

    // 3) output projection (HMMA bf16x3)
    gemm_hmma<<<dim3(DMODEL / BN, MROWS / BM), 256>>>(
        ath, atl, woh, wol, out, MROWS, DMODEL, DMODEL);
}

// round 4
// speedup vs baseline: 2.9972x; 2.0741x over previous
#include <cuda_runtime.h>
#include <cuda_bf16.h>
#include <stdint.h>

// ---------------------------------------------------------------------------
#define BATCH   2
#define SEQ     2048
#define DMODEL  1024
#define NHEADS  16
#define HDIM    64
#define MROWS   4096
#define QKV_N   3072

// ---------------------------------------------------------------------------
// Scratch (__device__ globals)
// ---------------------------------------------------------------------------
__device__ __nv_bfloat16 g_xh[(size_t)MROWS * DMODEL];
__device__ __nv_bfloat16 g_xl[(size_t)MROWS * DMODEL];
__device__ __nv_bfloat16 g_wqh[(size_t)QKV_N * DMODEL];
__device__ __nv_bfloat16 g_wql[(size_t)QKV_N * DMODEL];
__device__ __nv_bfloat16 g_woh[(size_t)DMODEL * DMODEL];
__device__ __nv_bfloat16 g_wol[(size_t)DMODEL * DMODEL];
__device__ __nv_bfloat16 g_qkvh[(size_t)MROWS * QKV_N];
__device__ __nv_bfloat16 g_qkvl[(size_t)MROWS * QKV_N];
__device__ __nv_bfloat16 g_ath[(size_t)MROWS * DMODEL];
__device__ __nv_bfloat16 g_atl[(size_t)MROWS * DMODEL];

// ---------------------------------------------------------------------------
// PTX helpers (all sm_80+ — safe on compute_103)
// ---------------------------------------------------------------------------
__device__ __forceinline__ uint32_t smem_u32(const void* p) {
    uint32_t a;
    asm("{ .reg .u64 t; cvta.to.shared.u64 t, %1; cvt.u32.u64 %0, t; }" : "=r"(a) : "l"(p));
    return a;
}
__device__ __forceinline__ void ldsm_x4(uint32_t* r, uint32_t addr) {
    asm volatile("ldmatrix.sync.aligned.m8n8.x4.shared.b16 {%0,%1,%2,%3}, [%4];"
                 : "=r"(r[0]), "=r"(r[1]), "=r"(r[2]), "=r"(r[3]) : "r"(addr));
}
__device__ __forceinline__ void ldsm_x4_t(uint32_t* r, uint32_t addr) {
    asm volatile("ldmatrix.sync.aligned.m8n8.x4.trans.shared.b16 {%0,%1,%2,%3}, [%4];"
                 : "=r"(r[0]), "=r"(r[1]), "=r"(r[2]), "=r"(r[3]) : "r"(addr));
}
__device__ __forceinline__ void mma16816(float* d, const uint32_t* a, const uint32_t* b) {
    asm volatile(
        "mma.sync.aligned.m16n8k16.row.col.f32.bf16.bf16.f32 "
        "{%0,%1,%2,%3}, {%4,%5,%6,%7}, {%8,%9}, {%0,%1,%2,%3};"
        : "+f"(d[0]), "+f"(d[1]), "+f"(d[2]), "+f"(d[3])
        : "r"(a[0]), "r"(a[1]), "r"(a[2]), "r"(a[3]), "r"(b[0]), "r"(b[1]));
}
__device__ __forceinline__ void cp16(uint32_t dst, const void* src) {
    asm volatile("cp.async.cg.shared.global [%0], [%1], 16;" :: "r"(dst), "l"(src));
}
#define CP_COMMIT() asm volatile("cp.async.commit_group;" ::: "memory")
#define CP_WAIT(n)  asm volatile("cp.async.wait_group %0;" :: "n"(n) : "memory")

__device__ __forceinline__ uint32_t pack_bf2(float a, float b) {
    __nv_bfloat162 t(__float2bfloat16(a), __float2bfloat16(b));
    return *(uint32_t*)&t;
}

// ---------------------------------------------------------------------------
// split fp32 -> bf16 hi + lo
// ---------------------------------------------------------------------------
__global__ __launch_bounds__(256) void split_bf16(
    const float* __restrict__ in, __nv_bfloat16* __restrict__ hi,
    __nv_bfloat16* __restrict__ lo, int n4)
{
    int i = blockIdx.x * 256 + threadIdx.x;
    if (i >= n4) return;
    float4 v = ((const float4*)in)[i];
    __nv_bfloat16 h0 = __float2bfloat16(v.x), h1 = __float2bfloat16(v.y);
    __nv_bfloat16 h2 = __float2bfloat16(v.z), h3 = __float2bfloat16(v.w);
    __nv_bfloat16 l0 = __float2bfloat16(v.x - __bfloat162float(h0));
    __nv_bfloat16 l1 = __float2bfloat16(v.y - __bfloat162float(h1));
    __nv_bfloat16 l2 = __float2bfloat16(v.z - __bfloat162float(h2));
    __nv_bfloat16 l3 = __float2bfloat16(v.w - __bfloat162float(h3));
    ((__nv_bfloat162*)hi)[2 * i]     = __nv_bfloat162(h0, h1);
    ((__nv_bfloat162*)hi)[2 * i + 1] = __nv_bfloat162(h2, h3);
    ((__nv_bfloat162*)lo)[2 * i]     = __nv_bfloat162(l0, l1);
    ((__nv_bfloat162*)lo)[2 * i + 1] = __nv_bfloat162(l2, l3);
}

// ---------------------------------------------------------------------------
// HMMA GEMM bf16x3-split, cp.async double-buffered.
// C[M,N] = A[M,K] * B[N,K]^T ; SPLIT=1 writes bf16 hi/lo instead of fp32.
// ---------------------------------------------------------------------------
#define BM 128
#define BN 128
#define BK 32
#define PITCH 40
#define GTILE (BM * PITCH)          // 5120 elems
#define GSTG  (4 * GTILE)           // 20480 elems / stage
#define GEMM_SMEM (2 * GSTG * 2)    // 81920 bytes

template<int SPLIT>
__global__ __launch_bounds__(256, 2) void gemm_hmma(
    const __nv_bfloat16* __restrict__ Ah, const __nv_bfloat16* __restrict__ Al,
    const __nv_bfloat16* __restrict__ Bh, const __nv_bfloat16* __restrict__ Bl,
    float* __restrict__ C, __nv_bfloat16* __restrict__ Ch, __nv_bfloat16* __restrict__ Cl,
    int M, int N, int K)
{
    extern __shared__ __nv_bfloat16 dsm[];
    const uint32_t sb = smem_u32(dsm);
    const int tid = threadIdx.x;
    const int wid = tid >> 5;
    const int lid = tid & 31;
    const int warp_m = (wid & 3) * 32;
    const int warp_n = (wid >> 2) * 64;
    const int brow = blockIdx.y * BM;
    const int bcol = blockIdx.x * BN;

    float acc[2][8][4];
#pragma unroll
    for (int mf = 0; mf < 2; mf++)
#pragma unroll
        for (int nf = 0; nf < 8; nf++)
#pragma unroll
            for (int c = 0; c < 4; c++) acc[mf][nf][c] = 0.f;

    const int a_row = warp_m + (lid & 15);
    const int a_ko  = (lid >> 4) * 8;
    const int b_row = (lid & 7) + ((lid >> 4) & 1) * 8;
    const int b_ko  = ((lid >> 3) & 1) * 8;

    const int r0 = tid >> 2, c0 = tid & 3;   // loader: rows r0, r0+64
    const int nk = K / BK;

    // ---- async tile loader ----
    auto issue = [&](int kt, int st) {
        size_t gA = (size_t)(brow + r0) * K + kt * BK + c0 * 8;
        size_t gB = (size_t)(bcol + r0) * K + kt * BK + c0 * 8;
        uint32_t d = sb + (uint32_t)(st * GSTG + r0 * PITCH + c0 * 8) * 2;
        uint32_t step = (uint32_t)(64 * PITCH) * 2;
        size_t gstep = (size_t)64 * K;
        cp16(d,                       Ah + gA);
        cp16(d + step,                Ah + gA + gstep);
        cp16(d + GTILE * 2,           Al + gA);
        cp16(d + GTILE * 2 + step,    Al + gA + gstep);
        cp16(d + 2 * GTILE * 2,        Bh + gB);
        cp16(d + 2 * GTILE * 2 + step, Bh + gB + gstep);
        cp16(d + 3 * GTILE * 2,        Bl + gB);
        cp16(d + 3 * GTILE * 2 + step, Bl + gB + gstep);
    };

    issue(0, 0); CP_COMMIT();

    for (int kt = 0; kt < nk; kt++) {
        int st = kt & 1;
        if (kt + 1 < nk) { issue(kt + 1, st ^ 1); CP_COMMIT(); CP_WAIT(1); }
        else             { CP_WAIT(0); }
        __syncthreads();

        uint32_t uAh = sb + (uint32_t)(st * GSTG) * 2;
        uint32_t uAl = uAh + GTILE * 2;
        uint32_t uBh = uAh + 2 * GTILE * 2;
        uint32_t uBl = uAh + 3 * GTILE * 2;

#pragma unroll
        for (int ks = 0; ks < 2; ks++) {
            uint32_t ah[2][4], al[2][4];
#pragma unroll
            for (int mf = 0; mf < 2; mf++) {
                uint32_t off = (uint32_t)((a_row + mf * 16) * PITCH + ks * 16 + a_ko) * 2;
                ldsm_x4(ah[mf], uAh + off);
                ldsm_x4(al[mf], uAl + off);
            }
#pragma unroll
            for (int np = 0; np < 4; np++) {
                uint32_t bh[4], bl[4];
                uint32_t off = (uint32_t)((warp_n + np * 16 + b_row) * PITCH + ks * 16 + b_ko) * 2;
                ldsm_x4(bh, uBh + off);
                ldsm_x4(bl, uBl + off);
#pragma unroll
                for (int f = 0; f < 2; f++) {
                    int nf = 2 * np + f;
#pragma unroll
                    for (int mf = 0; mf < 2; mf++) {
                        mma16816(acc[mf][nf], ah[mf], bh + 2 * f);
                        mma16816(acc[mf][nf], ah[mf], bl + 2 * f);
                        mma16816(acc[mf][nf], al[mf], bh + 2 * f);
                    }
                }
            }
        }
        __syncthreads();
    }

    // ---- epilogue ----
    const int er = lid >> 2;
    const int ec = (lid & 3) * 2;
#pragma unroll
    for (int mf = 0; mf < 2; mf++) {
#pragma unroll
        for (int nf = 0; nf < 8; nf++) {
            int row = brow + warp_m + mf * 16 + er;
            int col = bcol + warp_n + nf * 8 + ec;
            if (SPLIT) {
#pragma unroll
                for (int half = 0; half < 2; half++) {
                    float v0 = acc[mf][nf][2 * half];
                    float v1 = acc[mf][nf][2 * half + 1];
                    __nv_bfloat16 h0 = __float2bfloat16(v0), h1 = __float2bfloat16(v1);
                    __nv_bfloat16 l0 = __float2bfloat16(v0 - __bfloat162float(h0));
                    __nv_bfloat16 l1 = __float2bfloat16(v1 - __bfloat162float(h1));
                    size_t o = (size_t)(row + 8 * half) * N + col;
                    *(__nv_bfloat162*)(Ch + o) = __nv_bfloat162(h0, h1);
                    *(__nv_bfloat162*)(Cl + o) = __nv_bfloat162(l0, l1);
                }
            } else {
                *(float2*)&C[(size_t)row * N + col] = make_float2(acc[mf][nf][0], acc[mf][nf][1]);
                *(float2*)&C[(size_t)(row + 8) * N + col] = make_float2(acc[mf][nf][2], acc[mf][nf][3]);
            }
        }
    }
}

// ---------------------------------------------------------------------------
// Flash attention (causal) on HMMA, bf16x3 split, cp.async double-buffered.
// CTA = 128 threads (4 warps), Br = Bc = 64, D = 64.
// ---------------------------------------------------------------------------
#define FAP 72
#define FTILE (64 * FAP)          // 4608 elems
#define FSTG  (4 * FTILE)         // 18432 elems / stage
#define FA_SMEM (2 * FSTG * 2)    // 73728 bytes

__global__ __launch_bounds__(128) void flash_hmma(
    const __nv_bfloat16* __restrict__ qh_, const __nv_bfloat16* __restrict__ ql_,
    __nv_bfloat16* __restrict__ ath, __nv_bfloat16* __restrict__ atl)
{
    extern __shared__ __nv_bfloat16 fsm[];
    const uint32_t sb = smem_u32(fsm);
    const int tid = threadIdx.x;
    const int wid = tid >> 5;
    const int lane = tid & 31;
    const int qt = (int)gridDim.x - 1 - (int)blockIdx.x;
    const int bh = blockIdx.y;
    const int b = bh >> 4;
    const int h = bh & 15;
    const int rowbase = b * SEQ;
    const int q0 = qt * 64;
    const int warp_m = wid * 16;

    // ---- stage Q (hi into Kh slot, lo into Kl slot), then keep in regs ----
#pragma unroll
    for (int i = 0; i < 4; i++) {
        int v = tid + i * 128;
        int r = v >> 3, c = v & 7;
        size_t g = (size_t)(rowbase + q0 + r) * QKV_N + h * HDIM + c * 8;
        uint32_t d = sb + (uint32_t)(r * FAP + c * 8) * 2;
        cp16(d, qh_ + g);
        cp16(d + FTILE * 2, ql_ + g);
    }
    CP_COMMIT(); CP_WAIT(0);
    __syncthreads();

    uint32_t Qh[4][4], Ql[4][4];
#pragma unroll
    for (int ks = 0; ks < 4; ks++) {
        uint32_t addr = sb + (uint32_t)((warp_m + (lane & 15)) * FAP + (lane >> 4) * 8 + ks * 16) * 2;
        ldsm_x4(Qh[ks], addr);
        ldsm_x4(Ql[ks], addr + FTILE * 2);
    }
    __syncthreads();

    float oacc[8][4];
#pragma unroll
    for (int nd = 0; nd < 8; nd++)
#pragma unroll
        for (int c = 0; c < 4; c++) oacc[nd][c] = 0.f;
    float m0 = -1e30f, m1 = -1e30f, l0 = 0.f, l1 = 0.f;
    const float scale = 0.125f;

    auto issue_kv = [&](int jt, int st) {
#pragma unroll
        for (int i = 0; i < 4; i++) {
            int v = tid + i * 128;
            int r = v >> 3, c = v & 7;
            size_t g = (size_t)(rowbase + jt * 64 + r) * QKV_N + h * HDIM + c * 8;
            uint32_t d = sb + (uint32_t)(st * FSTG + r * FAP + c * 8) * 2;
            cp16(d,                 qh_ + g + DMODEL);       // Kh
            cp16(d + FTILE * 2,     ql_ + g + DMODEL);       // Kl
            cp16(d + 2 * FTILE * 2, qh_ + g + 2 * DMODEL);   // Vh
            cp16(d + 3 * FTILE * 2, ql_ + g + 2 * DMODEL);   // Vl
        }
    };

    issue_kv(0, 0); CP_COMMIT();

    const int qrow0 = warp_m + (lane >> 2);
    const int qrow1 = qrow0 + 8;

    for (int jt = 0; jt <= qt; jt++) {
        int st = jt & 1;
        if (jt < qt) { issue_kv(jt + 1, st ^ 1); CP_COMMIT(); CP_WAIT(1); }
        else         { CP_WAIT(0); }
        __syncthreads();

        uint32_t uKh = sb + (uint32_t)(st * FSTG) * 2;
        uint32_t uKl = uKh + FTILE * 2;
        uint32_t uVh = uKh + 2 * FTILE * 2;
        uint32_t uVl = uKh + 3 * FTILE * 2;

        // ---- S = Q K^T ----
        float sacc[8][4];
#pragma unroll
        for (int nf = 0; nf < 8; nf++)
#pragma unroll
            for (int c = 0; c < 4; c++) sacc[nf][c] = 0.f;

#pragma unroll
        for (int ks = 0; ks < 4; ks++) {
#pragma unroll
            for (int np = 0; np < 4; np++) {
                uint32_t kh[4], kl[4];
                uint32_t off = (uint32_t)(((lane & 7) + ((lane >> 4) & 1) * 8 + np * 16) * FAP
                                          + ((lane >> 3) & 1) * 8 + ks * 16) * 2;
                ldsm_x4(kh, uKh + off);
                ldsm_x4(kl, uKl + off);
#pragma unroll
                for (int f = 0; f < 2; f++) {
                    int nf = 2 * np + f;
                    mma16816(sacc[nf], Qh[ks], kh + 2 * f);
                    mma16816(sacc[nf], Qh[ks], kl + 2 * f);
                    mma16816(sacc[nf], Ql[ks], kh + 2 * f);
                }
            }
        }

        // ---- scale + causal mask ----
        if (jt == qt) {
#pragma unroll
            for (int nf = 0; nf < 8; nf++) {
                int col = nf * 8 + (lane & 3) * 2;
                sacc[nf][0] = (col     <= qrow0) ? sacc[nf][0] * scale : -1e30f;
                sacc[nf][1] = (col + 1 <= qrow0) ? sacc[nf][1] * scale : -1e30f;
                sacc[nf][2] = (col     <= qrow1) ? sacc[nf][2] * scale : -1e30f;
                sacc[nf][3] = (col + 1 <= qrow1) ? sacc[nf][3] * scale : -1e30f;
            }
        } else {
#pragma unroll
            for (int nf = 0; nf < 8; nf++)
#pragma unroll
                for (int c = 0; c < 4; c++) sacc[nf][c] *= scale;
        }

        // ---- online softmax (rows qrow0, qrow1; 4 lanes per row) ----
        float mx0 = -1e30f, mx1 = -1e30f;
#pragma unroll
        for (int nf = 0; nf < 8; nf++) {
            mx0 = fmaxf(mx0, fmaxf(sacc[nf][0], sacc[nf][1]));
            mx1 = fmaxf(mx1, fmaxf(sacc[nf][2], sacc[nf][3]));
        }
        mx0 = fmaxf(mx0, __shfl_xor_sync(0xffffffffu, mx0, 1));
        mx0 = fmaxf(mx0, __shfl_xor_sync(0xffffffffu, mx0, 2));
        mx1 = fmaxf(mx1, __shfl_xor_sync(0xffffffffu, mx1, 1));
        mx1 = fmaxf(mx1, __shfl_xor_sync(0xffffffffu, mx1, 2));
        float mn0 = fmaxf(m0, mx0), mn1 = fmaxf(m1, mx1);
        float al0 = __expf(m0 - mn0), al1 = __expf(m1 - mn1);
        float s0 = 0.f, s1 = 0.f;
#pragma unroll
        for (int nf = 0; nf < 8; nf++) {
            sacc[nf][0] = __expf(sacc[nf][0] - mn0); s0 += sacc[nf][0];
            sacc[nf][1] = __expf(sacc[nf][1] - mn0); s0 += sacc[nf][1];
            sacc[nf][2] = __expf(sacc[nf][2] - mn1); s1 += sacc[nf][2];
            sacc[nf][3] = __expf(sacc[nf][3] - mn1); s1 += sacc[nf][3];
        }
        s0 += __shfl_xor_sync(0xffffffffu, s0, 1);
        s0 += __shfl_xor_sync(0xffffffffu, s0, 2);
        s1 += __shfl_xor_sync(0xffffffffu, s1, 1);
        s1 += __shfl_xor_sync(0xffffffffu, s1, 2);
        l0 = l0 * al0 + s0; m0 = mn0;
        l1 = l1 * al1 + s1; m1 = mn1;
#pragma unroll
        for (int nd = 0; nd < 8; nd++) {
            oacc[nd][0] *= al0; oacc[nd][1] *= al0;
            oacc[nd][2] *= al1; oacc[nd][3] *= al1;
        }

        // ---- O += P V  (P from register fragments) ----
#pragma unroll
        for (int kb = 0; kb < 4; kb++) {
            uint32_t pah[4], pal[4];
            {
                float v00 = sacc[2 * kb][0],     v01 = sacc[2 * kb][1];
                float v02 = sacc[2 * kb][2],     v03 = sacc[2 * kb][3];
                float v10 = sacc[2 * kb + 1][0], v11 = sacc[2 * kb + 1][1];
                float v12 = sacc[2 * kb + 1][2], v13 = sacc[2 * kb + 1][3];
                pah[0] = pack_bf2(v00, v01); pah[1] = pack_bf2(v02, v03);
                pah[2] = pack_bf2(v10, v11); pah[3] = pack_bf2(v12, v13);
                float r00 = v00 - __bfloat162float(__float2bfloat16(v00));
                float r01 = v01 - __bfloat162float(__float2bfloat16(v01));
                float r02 = v02 - __bfloat162float(__float2bfloat16(v02));
                float r03 = v03 - __bfloat162float(__float2bfloat16(v03));
                float r10 = v10 - __bfloat162float(__float2bfloat16(v10));
                float r11 = v11 - __bfloat162float(__float2bfloat16(v11));
                float r12 = v12 - __bfloat162float(__float2bfloat16(v12));
                float r13 = v13 - __bfloat162float(__float2bfloat16(v13));
                pal[0] = pack_bf2(r00, r01); pal[1] = pack_bf2(r02, r03);
                pal[2] = pack_bf2(r10, r11); pal[3] = pack_bf2(r12, r13);
            }
#pragma unroll
            for (int ndp = 0; ndp < 4; ndp++) {
                uint32_t vh[4], vl[4];
                uint32_t off = (uint32_t)((kb * 16 + (lane & 7) + ((lane >> 3) & 1) * 8) * FAP
                                          + ndp * 16 + ((lane >> 4) & 1) * 8) * 2;
                ldsm_x4_t(vh, uVh + off);
                ldsm_x4_t(vl, uVl + off);
#pragma unroll
                for (int f = 0; f < 2; f++) {
                    int nd = 2 * ndp + f;
                    mma16816(oacc[nd], pah, vh + 2 * f);
                    mma16816(oacc[nd], pah, vl + 2 * f);
                    mma16816(oacc[nd], pal, vh + 2 * f);
                }
            }
        }
        __syncthreads();
    }

    // ---- epilogue: normalize, split bf16 hi/lo ----
    float inv0 = 1.f / l0, inv1 = 1.f / l1;
    int grow0 = rowbase + q0 + qrow0;
#pragma unroll
    for (int nd = 0; nd < 8; nd++) {
        int col = h * HDIM + nd * 8 + (lane & 3) * 2;
#pragma unroll
        for (int half = 0; half < 2; half++) {
            float v0 = oacc[nd][2 * half]     * (half ? inv1 : inv0);
            float v1 = oacc[nd][2 * half + 1] * (half ? inv1 : inv0);
            __nv_bfloat16 h0 = __float2bfloat16(v0), h1 = __float2bfloat16(v1);
            __nv_bfloat16 l0b = __float2bfloat16(v0 - __bfloat162float(h0));
            __nv_bfloat16 l1b = __float2bfloat16(v1 - __bfloat162float(h1));
            size_t o = (size_t)(grow0 + 8 * half) * DMODEL + col;
            *(__nv_bfloat162*)(ath + o) = __nv_bfloat162(h0, h1);
            *(__nv_bfloat162*)(atl + o) = __nv_bfloat162(l0b, l1b);
        }
    }
}

// ---------------------------------------------------------------------------
// Launch
// ---------------------------------------------------------------------------
extern "C" void kernel_launch(void* const* d_in, const int* in_sizes, int n_in,
                              void* d_out, int out_size)
{
    (void)in_sizes; (void)n_in; (void)out_size;
    const float* x     = (const float*)d_in[0];
    const float* W_qkv = (const float*)d_in[1];
    const float* W_out = (const float*)d_in[2];
    float* out = (float*)d_out;

    __nv_bfloat16 *xh, *xl, *wqh, *wql, *woh, *wol, *qkvh, *qkvl, *ath, *atl;
    cudaGetSymbolAddress((void**)&xh, g_xh);
    cudaGetSymbolAddress((void**)&xl, g_xl);
    cudaGetSymbolAddress((void**)&wqh, g_wqh);
    cudaGetSymbolAddress((void**)&wql, g_wql);
    cudaGetSymbolAddress((void**)&woh, g_woh);
    cudaGetSymbolAddress((void**)&wol, g_wol);
    cudaGetSymbolAddress((void**)&qkvh, g_qkvh);
    cudaGetSymbolAddress((void**)&qkvl, g_qkvl);
    cudaGetSymbolAddress((void**)&ath, g_ath);
    cudaGetSymbolAddress((void**)&atl, g_atl);

    cudaFuncSetAttribute(gemm_hmma<0>, cudaFuncAttributeMaxDynamicSharedMemorySize, GEMM_SMEM);
    cudaFuncSetAttribute(gemm_hmma<1>, cudaFuncAttributeMaxDynamicSharedMemorySize, GEMM_SMEM);
    cudaFuncSetAttribute(flash_hmma, cudaFuncAttributeMaxDynamicSharedMemorySize, FA_SMEM);

    split_bf16<<<(MROWS * DMODEL / 4 + 255) / 256, 256>>>(x, xh, xl, MROWS * DMODEL / 4);
    split_bf16<<<(QKV_N * DMODEL / 4 + 255) / 256, 256>>>(W_qkv, wqh, wql, QKV_N * DMODEL / 4);
    split_bf16<<<(DMODEL * DMODEL / 4 + 255) / 256, 256>>>(W_out, woh, wol, DMODEL * DMODEL / 4);

    // 1) QKV projection -> bf16 hi/lo directly
    gemm_hmma<1><<<dim3(QKV_N / BN, MROWS / BM), 256, GEMM_SMEM>>>(
        xh, xl, wqh, wql, nullptr, qkvh, qkvl, MROWS, QKV_N, DMODEL);

    // 2) causal flash attention (HMMA) -> bf16 hi/lo
    flash_hmma<<<dim3(SEQ / 64, BATCH * NHEADS), 128, FA_SMEM>>>(qkvh, qkvl, ath, atl);

    // 3) output projection -> fp32
    gemm_hmma<0><<<dim3(DMODEL / BN, MROWS / BM), 256, GEMM_SMEM>>>(
        ath, atl, woh, wol, out, nullptr, nullptr, MROWS, DMODEL, DMODEL);
}

// round 6
// speedup vs baseline: 3.4998x; 1.1677x over previous
#include <cuda_runtime.h>
#include <cuda_bf16.h>
#include <stdint.h>

// ---------------------------------------------------------------------------
#define BATCH   2
#define SEQ     2048
#define DMODEL  1024
#define NHEADS  16
#define HDIM    64
#define MROWS   4096
#define QKV_N   3072

// ---------------------------------------------------------------------------
// Scratch (__device__ globals)
// ---------------------------------------------------------------------------
__device__ __nv_bfloat16 g_xh[(size_t)MROWS * DMODEL];
__device__ __nv_bfloat16 g_xl[(size_t)MROWS * DMODEL];
__device__ __nv_bfloat16 g_wqh[(size_t)QKV_N * DMODEL];
__device__ __nv_bfloat16 g_wql[(size_t)QKV_N * DMODEL];
__device__ __nv_bfloat16 g_woh[(size_t)DMODEL * DMODEL];
__device__ __nv_bfloat16 g_wol[(size_t)DMODEL * DMODEL];
__device__ __nv_bfloat16 g_qkvh[(size_t)MROWS * QKV_N];
__device__ __nv_bfloat16 g_qkvl[(size_t)MROWS * QKV_N];
__device__ __nv_bfloat16 g_ath[(size_t)MROWS * DMODEL];
__device__ __nv_bfloat16 g_atl[(size_t)MROWS * DMODEL];

// ---------------------------------------------------------------------------
// PTX helpers (all sm_80+ — safe on compute_103)
// ---------------------------------------------------------------------------
__device__ __forceinline__ uint32_t smem_u32(const void* p) {
    uint32_t a;
    asm("{ .reg .u64 t; cvta.to.shared.u64 t, %1; cvt.u32.u64 %0, t; }" : "=r"(a) : "l"(p));
    return a;
}
__device__ __forceinline__ void ldsm_x4(uint32_t* r, uint32_t addr) {
    asm volatile("ldmatrix.sync.aligned.m8n8.x4.shared.b16 {%0,%1,%2,%3}, [%4];"
                 : "=r"(r[0]), "=r"(r[1]), "=r"(r[2]), "=r"(r[3]) : "r"(addr));
}
__device__ __forceinline__ void ldsm_x4_t(uint32_t* r, uint32_t addr) {
    asm volatile("ldmatrix.sync.aligned.m8n8.x4.trans.shared.b16 {%0,%1,%2,%3}, [%4];"
                 : "=r"(r[0]), "=r"(r[1]), "=r"(r[2]), "=r"(r[3]) : "r"(addr));
}
__device__ __forceinline__ void mma16816(float* d, const uint32_t* a, const uint32_t* b) {
    asm volatile(
        "mma.sync.aligned.m16n8k16.row.col.f32.bf16.bf16.f32 "
        "{%0,%1,%2,%3}, {%4,%5,%6,%7}, {%8,%9}, {%0,%1,%2,%3};"
        : "+f"(d[0]), "+f"(d[1]), "+f"(d[2]), "+f"(d[3])
        : "r"(a[0]), "r"(a[1]), "r"(a[2]), "r"(a[3]), "r"(b[0]), "r"(b[1]));
}
__device__ __forceinline__ void cp16(uint32_t dst, const void* src) {
    asm volatile("cp.async.cg.shared.global [%0], [%1], 16;" :: "r"(dst), "l"(src));
}
#define CP_COMMIT() asm volatile("cp.async.commit_group;" ::: "memory")
#define CP_WAIT(n)  asm volatile("cp.async.wait_group %0;" :: "n"(n) : "memory")

__device__ __forceinline__ uint32_t pack_bf2(float a, float b) {
    __nv_bfloat162 t(__float2bfloat16(a), __float2bfloat16(b));
    return *(uint32_t*)&t;
}

// ---------------------------------------------------------------------------
// split fp32 -> bf16 hi + lo
// ---------------------------------------------------------------------------
__global__ __launch_bounds__(256) void split_bf16(
    const float* __restrict__ in, __nv_bfloat16* __restrict__ hi,
    __nv_bfloat16* __restrict__ lo, int n4)
{
    int i = blockIdx.x * 256 + threadIdx.x;
    if (i >= n4) return;
    float4 v = ((const float4*)in)[i];
    __nv_bfloat16 h0 = __float2bfloat16(v.x), h1 = __float2bfloat16(v.y);
    __nv_bfloat16 h2 = __float2bfloat16(v.z), h3 = __float2bfloat16(v.w);
    __nv_bfloat16 l0 = __float2bfloat16(v.x - __bfloat162float(h0));
    __nv_bfloat16 l1 = __float2bfloat16(v.y - __bfloat162float(h1));
    __nv_bfloat16 l2 = __float2bfloat16(v.z - __bfloat162float(h2));
    __nv_bfloat16 l3 = __float2bfloat16(v.w - __bfloat162float(h3));
    ((__nv_bfloat162*)hi)[2 * i]     = __nv_bfloat162(h0, h1);
    ((__nv_bfloat162*)hi)[2 * i + 1] = __nv_bfloat162(h2, h3);
    ((__nv_bfloat162*)lo)[2 * i]     = __nv_bfloat162(l0, l1);
    ((__nv_bfloat162*)lo)[2 * i + 1] = __nv_bfloat162(l2, l3);
}

// ---------------------------------------------------------------------------
// HMMA GEMM bf16x3-split, 3-stage cp.async pipeline, XOR-swizzled smem.
// C[M,N] = A[M,K] * B[N,K]^T ; SPLIT=1 writes bf16 hi/lo.
// Tile rows are 32 bf16 (64B); swizzle: chunk' = c ^ ((row>>1)&3).
// ---------------------------------------------------------------------------
#define BM 128
#define BN 128
#define BK 32
#define GT_B  (BM * BK * 2)        // 8192 bytes / tile
#define GSTG_B (4 * GT_B)          // 32768 bytes / stage
#define GEMM_SMEM (3 * GSTG_B)     // 98304

__device__ __forceinline__ uint32_t gswz(int row, int c) {  // byte offset
    return (uint32_t)(row * BK + ((c ^ ((row >> 1) & 3)) << 3)) * 2;
}

template<int SPLIT>
__global__ __launch_bounds__(256, 2) void gemm_hmma(
    const __nv_bfloat16* __restrict__ Ah, const __nv_bfloat16* __restrict__ Al,
    const __nv_bfloat16* __restrict__ Bh, const __nv_bfloat16* __restrict__ Bl,
    float* __restrict__ C, __nv_bfloat16* __restrict__ Ch, __nv_bfloat16* __restrict__ Cl,
    int M, int N, int K)
{
    extern __shared__ __nv_bfloat16 dsm[];
    const uint32_t sb = smem_u32(dsm);
    const int tid = threadIdx.x;
    const int wid = tid >> 5;
    const int lid = tid & 31;
    const int warp_m = (wid & 3) * 32;
    const int warp_n = (wid >> 2) * 64;
    const int brow = blockIdx.y * BM;
    const int bcol = blockIdx.x * BN;

    float acc[2][8][4];
#pragma unroll
    for (int mf = 0; mf < 2; mf++)
#pragma unroll
        for (int nf = 0; nf < 8; nf++)
#pragma unroll
            for (int c = 0; c < 4; c++) acc[mf][nf][c] = 0.f;

    const int r0 = tid >> 2, c0 = tid & 3;
    const uint32_t o0 = gswz(r0, c0);
    const uint32_t o1 = gswz(r0 + 64, c0);
    const int nk = K / BK;

    auto issue = [&](int kt, int st) {
        size_t gA = (size_t)(brow + r0) * K + kt * BK + c0 * 8;
        size_t gB = (size_t)(bcol + r0) * K + kt * BK + c0 * 8;
        size_t gs = (size_t)64 * K;
        uint32_t d = sb + st * GSTG_B;
        cp16(d + o0,            Ah + gA);
        cp16(d + o1,            Ah + gA + gs);
        cp16(d + GT_B + o0,     Al + gA);
        cp16(d + GT_B + o1,     Al + gA + gs);
        cp16(d + 2 * GT_B + o0, Bh + gB);
        cp16(d + 2 * GT_B + o1, Bh + gB + gs);
        cp16(d + 3 * GT_B + o0, Bl + gB);
        cp16(d + 3 * GT_B + o1, Bl + gB + gs);
    };

    issue(0, 0); CP_COMMIT();
    issue(1, 1); CP_COMMIT();

    const int a_r = lid & 15;
    const int a_c = lid >> 4;          // chunk half
    const int b_r = (lid & 7) + ((lid >> 4) & 1) * 8;
    const int b_c = (lid >> 3) & 1;

    for (int kt = 0; kt < nk; kt++) {
        int st = kt - (kt / 3) * 3;
        CP_WAIT(1);
        __syncthreads();
        if (kt + 2 < nk) { int k2 = kt + 2; issue(k2, k2 - (k2 / 3) * 3); }
        CP_COMMIT();

        uint32_t uAh = sb + st * GSTG_B;
        uint32_t uAl = uAh + GT_B;
        uint32_t uBh = uAh + 2 * GT_B;
        uint32_t uBl = uAh + 3 * GT_B;

#pragma unroll
        for (int ks = 0; ks < 2; ks++) {
            uint32_t ah[2][4], al[2][4];
#pragma unroll
            for (int mf = 0; mf < 2; mf++) {
                uint32_t off = gswz(warp_m + mf * 16 + a_r, ks * 2 + a_c);
                ldsm_x4(ah[mf], uAh + off);
                ldsm_x4(al[mf], uAl + off);
            }
#pragma unroll
            for (int np = 0; np < 4; np++) {
                uint32_t bh[4], bl[4];
                uint32_t off = gswz(warp_n + np * 16 + b_r, ks * 2 + b_c);
                ldsm_x4(bh, uBh + off);
                ldsm_x4(bl, uBl + off);
#pragma unroll
                for (int f = 0; f < 2; f++) {
                    int nf = 2 * np + f;
#pragma unroll
                    for (int mf = 0; mf < 2; mf++) {
                        mma16816(acc[mf][nf], ah[mf], bh + 2 * f);
                        mma16816(acc[mf][nf], ah[mf], bl + 2 * f);
                        mma16816(acc[mf][nf], al[mf], bh + 2 * f);
                    }
                }
            }
        }
    }

    const int er = lid >> 2;
    const int ec = (lid & 3) * 2;
#pragma unroll
    for (int mf = 0; mf < 2; mf++) {
#pragma unroll
        for (int nf = 0; nf < 8; nf++) {
            int row = brow + warp_m + mf * 16 + er;
            int col = bcol + warp_n + nf * 8 + ec;
            if (SPLIT) {
#pragma unroll
                for (int half = 0; half < 2; half++) {
                    float v0 = acc[mf][nf][2 * half];
                    float v1 = acc[mf][nf][2 * half + 1];
                    __nv_bfloat16 h0 = __float2bfloat16(v0), h1 = __float2bfloat16(v1);
                    __nv_bfloat16 l0 = __float2bfloat16(v0 - __bfloat162float(h0));
                    __nv_bfloat16 l1 = __float2bfloat16(v1 - __bfloat162float(h1));
                    size_t o = (size_t)(row + 8 * half) * N + col;
                    *(__nv_bfloat162*)(Ch + o) = __nv_bfloat162(h0, h1);
                    *(__nv_bfloat162*)(Cl + o) = __nv_bfloat162(l0, l1);
                }
            } else {
                *(float2*)&C[(size_t)row * N + col] = make_float2(acc[mf][nf][0], acc[mf][nf][1]);
                *(float2*)&C[(size_t)(row + 8) * N + col] = make_float2(acc[mf][nf][2], acc[mf][nf][3]);
            }
        }
    }
}

// ---------------------------------------------------------------------------
// Flash attention (causal) on HMMA, 3-stage cp.async pipeline, XOR swizzle.
// CTA = 128 threads (4 warps), Br = Bc = 64, D = 64.
// Tile rows are 64 bf16 (128B); swizzle: chunk' = c ^ (row&7).
// ---------------------------------------------------------------------------
#define FT_B   (64 * 64 * 2)        // 8192 bytes / tile
#define FSTG_B (4 * FT_B)           // 32768 bytes / stage
#define FA_SMEM (3 * FSTG_B)        // 98304

__device__ __forceinline__ uint32_t fswz(int row, int c) {  // byte offset
    return (uint32_t)(row * 64 + ((c ^ (row & 7)) << 3)) * 2;
}

__global__ __launch_bounds__(128, 2) void flash_hmma(
    const __nv_bfloat16* __restrict__ qh_, const __nv_bfloat16* __restrict__ ql_,
    __nv_bfloat16* __restrict__ ath, __nv_bfloat16* __restrict__ atl)
{
    extern __shared__ __nv_bfloat16 fsm[];
    const uint32_t sb = smem_u32(fsm);
    const int tid = threadIdx.x;
    const int wid = tid >> 5;
    const int lane = tid & 31;
    const int qt = (int)gridDim.x - 1 - (int)blockIdx.x;
    const int bh = blockIdx.y;
    const int b = bh >> 4;
    const int h = bh & 15;
    const int rowbase = b * SEQ;
    const int q0 = qt * 64;
    const int warp_m = wid * 16;

    // ---- stage Q into stage 0 (hi, lo slots), read to regs ----
#pragma unroll
    for (int i = 0; i < 4; i++) {
        int v = tid + i * 128;
        int r = v >> 3, c = v & 7;
        size_t g = (size_t)(rowbase + q0 + r) * QKV_N + h * HDIM + c * 8;
        uint32_t o = fswz(r, c);
        cp16(sb + o, qh_ + g);
        cp16(sb + FT_B + o, ql_ + g);
    }
    CP_COMMIT(); CP_WAIT(0);
    __syncthreads();

    uint32_t Qh[4][4], Ql[4][4];
#pragma unroll
    for (int ks = 0; ks < 4; ks++) {
        uint32_t off = fswz(warp_m + (lane & 15), ks * 2 + (lane >> 4));
        ldsm_x4(Qh[ks], sb + off);
        ldsm_x4(Ql[ks], sb + FT_B + off);
    }
    __syncthreads();

    float oacc[8][4];
#pragma unroll
    for (int nd = 0; nd < 8; nd++)
#pragma unroll
        for (int c = 0; c < 4; c++) oacc[nd][c] = 0.f;
    float m0 = -1e30f, m1 = -1e30f, l0 = 0.f, l1 = 0.f;
    const float scale = 0.125f;

    auto issue_kv = [&](int jt, int st) {
#pragma unroll
        for (int i = 0; i < 4; i++) {
            int v = tid + i * 128;
            int r = v >> 3, c = v & 7;
            size_t g = (size_t)(rowbase + jt * 64 + r) * QKV_N + h * HDIM + c * 8;
            uint32_t d = sb + st * FSTG_B + fswz(r, c);
            cp16(d,            qh_ + g + DMODEL);       // Kh
            cp16(d + FT_B,     ql_ + g + DMODEL);       // Kl
            cp16(d + 2 * FT_B, qh_ + g + 2 * DMODEL);   // Vh
            cp16(d + 3 * FT_B, ql_ + g + 2 * DMODEL);   // Vl
        }
    };

    issue_kv(0, 0); CP_COMMIT();
    if (qt >= 1) issue_kv(1, 1);
    CP_COMMIT();

    const int qrow0 = warp_m + (lane >> 2);
    const int qrow1 = qrow0 + 8;
    const int k_r = (lane & 7) + ((lane >> 4) & 1) * 8;
    const int k_c = (lane >> 3) & 1;
    const int v_r = (lane & 7) + ((lane >> 3) & 1) * 8;
    const int v_c = (lane >> 4) & 1;

    for (int jt = 0; jt <= qt; jt++) {
        int st = jt - (jt / 3) * 3;
        CP_WAIT(1);
        __syncthreads();
        if (jt + 2 <= qt) { int j2 = jt + 2; issue_kv(j2, j2 - (j2 / 3) * 3); }
        CP_COMMIT();

        uint32_t uKh = sb + st * FSTG_B;
        uint32_t uKl = uKh + FT_B;
        uint32_t uVh = uKh + 2 * FT_B;
        uint32_t uVl = uKh + 3 * FT_B;

        // ---- S = Q K^T ----
        float sacc[8][4];
#pragma unroll
        for (int nf = 0; nf < 8; nf++)
#pragma unroll
            for (int c = 0; c < 4; c++) sacc[nf][c] = 0.f;

#pragma unroll
        for (int ks = 0; ks < 4; ks++) {
#pragma unroll
            for (int np = 0; np < 4; np++) {
                uint32_t kh[4], kl[4];
                uint32_t off = fswz(np * 16 + k_r, ks * 2 + k_c);
                ldsm_x4(kh, uKh + off);
                ldsm_x4(kl, uKl + off);
#pragma unroll
                for (int f = 0; f < 2; f++) {
                    int nf = 2 * np + f;
                    mma16816(sacc[nf], Qh[ks], kh + 2 * f);
                    mma16816(sacc[nf], Qh[ks], kl + 2 * f);
                    mma16816(sacc[nf], Ql[ks], kh + 2 * f);
                }
            }
        }

        // ---- scale + causal mask ----
        if (jt == qt) {
#pragma unroll
            for (int nf = 0; nf < 8; nf++) {
                int col = nf * 8 + (lane & 3) * 2;
                sacc[nf][0] = (col     <= qrow0) ? sacc[nf][0] * scale : -1e30f;
                sacc[nf][1] = (col + 1 <= qrow0) ? sacc[nf][1] * scale : -1e30f;
                sacc[nf][2] = (col     <= qrow1) ? sacc[nf][2] * scale : -1e30f;
                sacc[nf][3] = (col + 1 <= qrow1) ? sacc[nf][3] * scale : -1e30f;
            }
        } else {
#pragma unroll
            for (int nf = 0; nf < 8; nf++)
#pragma unroll
                for (int c = 0; c < 4; c++) sacc[nf][c] *= scale;
        }

        // ---- online softmax ----
        float mx0 = -1e30f, mx1 = -1e30f;
#pragma unroll
        for (int nf = 0; nf < 8; nf++) {
            mx0 = fmaxf(mx0, fmaxf(sacc[nf][0], sacc[nf][1]));
            mx1 = fmaxf(mx1, fmaxf(sacc[nf][2], sacc[nf][3]));
        }
        mx0 = fmaxf(mx0, __shfl_xor_sync(0xffffffffu, mx0, 1));
        mx0 = fmaxf(mx0, __shfl_xor_sync(0xffffffffu, mx0, 2));
        mx1 = fmaxf(mx1, __shfl_xor_sync(0xffffffffu, mx1, 1));
        mx1 = fmaxf(mx1, __shfl_xor_sync(0xffffffffu, mx1, 2));
        float mn0 = fmaxf(m0, mx0), mn1 = fmaxf(m1, mx1);
        float al0 = __expf(m0 - mn0), al1 = __expf(m1 - mn1);
        float s0 = 0.f, s1 = 0.f;
#pragma unroll
        for (int nf = 0; nf < 8; nf++) {
            sacc[nf][0] = __expf(sacc[nf][0] - mn0); s0 += sacc[nf][0];
            sacc[nf][1] = __expf(sacc[nf][1] - mn0); s0 += sacc[nf][1];
            sacc[nf][2] = __expf(sacc[nf][2] - mn1); s1 += sacc[nf][2];
            sacc[nf][3] = __expf(sacc[nf][3] - mn1); s1 += sacc[nf][3];
        }
        s0 += __shfl_xor_sync(0xffffffffu, s0, 1);
        s0 += __shfl_xor_sync(0xffffffffu, s0, 2);
        s1 += __shfl_xor_sync(0xffffffffu, s1, 1);
        s1 += __shfl_xor_sync(0xffffffffu, s1, 2);
        l0 = l0 * al0 + s0; m0 = mn0;
        l1 = l1 * al1 + s1; m1 = mn1;
#pragma unroll
        for (int nd = 0; nd < 8; nd++) {
            oacc[nd][0] *= al0; oacc[nd][1] *= al0;
            oacc[nd][2] *= al1; oacc[nd][3] *= al1;
        }

        // ---- O += P V ----
#pragma unroll
        for (int kb = 0; kb < 4; kb++) {
            uint32_t pah[4], pal[4];
            {
                float v00 = sacc[2 * kb][0],     v01 = sacc[2 * kb][1];
                float v02 = sacc[2 * kb][2],     v03 = sacc[2 * kb][3];
                float v10 = sacc[2 * kb + 1][0], v11 = sacc[2 * kb + 1][1];
                float v12 = sacc[2 * kb + 1][2], v13 = sacc[2 * kb + 1][3];
                pah[0] = pack_bf2(v00, v01); pah[1] = pack_bf2(v02, v03);
                pah[2] = pack_bf2(v10, v11); pah[3] = pack_bf2(v12, v13);
                pal[0] = pack_bf2(v00 - __bfloat162float(__float2bfloat16(v00)),
                                  v01 - __bfloat162float(__float2bfloat16(v01)));
                pal[1] = pack_bf2(v02 - __bfloat162float(__float2bfloat16(v02)),
                                  v03 - __bfloat162float(__float2bfloat16(v03)));
                pal[2] = pack_bf2(v10 - __bfloat162float(__float2bfloat16(v10)),
                                  v11 - __bfloat162float(__float2bfloat16(v11)));
                pal[3] = pack_bf2(v12 - __bfloat162float(__float2bfloat16(v12)),
                                  v13 - __bfloat162float(__float2bfloat16(v13)));
            }
#pragma unroll
            for (int ndp = 0; ndp < 4; ndp++) {
                uint32_t vh[4], vl[4];
                uint32_t off = fswz(kb * 16 + v_r, ndp * 2 + v_c);
                ldsm_x4_t(vh, uVh + off);
                ldsm_x4_t(vl, uVl + off);
#pragma unroll
                for (int f = 0; f < 2; f++) {
                    int nd = 2 * ndp + f;
                    mma16816(oacc[nd], pah, vh + 2 * f);
                    mma16816(oacc[nd], pah, vl + 2 * f);
                    mma16816(oacc[nd], pal, vh + 2 * f);
                }
            }
        }
    }

    // ---- epilogue ----
    float inv0 = 1.f / l0, inv1 = 1.f / l1;
    int grow0 = rowbase + q0 + qrow0;
#pragma unroll
    for (int nd = 0; nd < 8; nd++) {
        int col = h * HDIM + nd * 8 + (lane & 3) * 2;
#pragma unroll
        for (int half = 0; half < 2; half++) {
            float v0 = oacc[nd][2 * half]     * (half ? inv1 : inv0);
            float v1 = oacc[nd][2 * half + 1] * (half ? inv1 : inv0);
            __nv_bfloat16 h0 = __float2bfloat16(v0), h1 = __float2bfloat16(v1);
            __nv_bfloat16 l0b = __float2bfloat16(v0 - __bfloat162float(h0));
            __nv_bfloat16 l1b = __float2bfloat16(v1 - __bfloat162float(h1));
            size_t o = (size_t)(grow0 + 8 * half) * DMODEL + col;
            *(__nv_bfloat162*)(ath + o) = __nv_bfloat162(h0, h1);
            *(__nv_bfloat162*)(atl + o) = __nv_bfloat162(l0b, l1b);
        }
    }
}

// ---------------------------------------------------------------------------
// Launch
// ---------------------------------------------------------------------------
extern "C" void kernel_launch(void* const* d_in, const int* in_sizes, int n_in,
                              void* d_out, int out_size)
{
    (void)in_sizes; (void)n_in; (void)out_size;
    const float* x     = (const float*)d_in[0];
    const float* W_qkv = (const float*)d_in[1];
    const float* W_out = (const float*)d_in[2];
    float* out = (float*)d_out;

    __nv_bfloat16 *xh, *xl, *wqh, *wql, *woh, *wol, *qkvh, *qkvl, *ath, *atl;
    cudaGetSymbolAddress((void**)&xh, g_xh);
    cudaGetSymbolAddress((void**)&xl, g_xl);
    cudaGetSymbolAddress((void**)&wqh, g_wqh);
    cudaGetSymbolAddress((void**)&wql, g_wql);
    cudaGetSymbolAddress((void**)&woh, g_woh);
    cudaGetSymbolAddress((void**)&wol, g_wol);
    cudaGetSymbolAddress((void**)&qkvh, g_qkvh);
    cudaGetSymbolAddress((void**)&qkvl, g_qkvl);
    cudaGetSymbolAddress((void**)&ath, g_ath);
    cudaGetSymbolAddress((void**)&atl, g_atl);

    cudaFuncSetAttribute(gemm_hmma<0>, cudaFuncAttributeMaxDynamicSharedMemorySize, GEMM_SMEM);
    cudaFuncSetAttribute(gemm_hmma<1>, cudaFuncAttributeMaxDynamicSharedMemorySize, GEMM_SMEM);
    cudaFuncSetAttribute(flash_hmma, cudaFuncAttributeMaxDynamicSharedMemorySize, FA_SMEM);

    split_bf16<<<(MROWS * DMODEL / 4 + 255) / 256, 256>>>(x, xh, xl, MROWS * DMODEL / 4);
    split_bf16<<<(QKV_N * DMODEL / 4 + 255) / 256, 256>>>(W_qkv, wqh, wql, QKV_N * DMODEL / 4);
    split_bf16<<<(DMODEL * DMODEL / 4 + 255) / 256, 256>>>(W_out, woh, wol, DMODEL * DMODEL / 4);

    gemm_hmma<1><<<dim3(QKV_N / BN, MROWS / BM), 256, GEMM_SMEM>>>(
        xh, xl, wqh, wql, nullptr, qkvh, qkvl, MROWS, QKV_N, DMODEL);

    flash_hmma<<<dim3(SEQ / 64, BATCH * NHEADS), 128, FA_SMEM>>>(qkvh, qkvl, ath, atl);

    gemm_hmma<0><<<dim3(DMODEL / BN, MROWS / BM), 256, GEMM_SMEM>>>(
        ath, atl, woh, wol, out, nullptr, nullptr, MROWS, DMODEL, DMODEL);
}